// round 13
// baseline (speedup 1.0000x reference)
#include <cuda_runtime.h>
#include <math.h>
#include <stdint.h>

#define BB   1024
#define NN   128
#define EE   1024
#define HH   128
#define LL   4
#define INDIM 16
#define DIN  19
#define EDIM 4
#define NH   (NN*HH)      // 16384
#define HSQ  (HH*HH)      // 16384
#define ASTR 132

// ---------------- device scratch ----------------
__device__ float  g_mag0[(size_t)BB*NH];
__device__ float  g_ph0 [(size_t)BB*NH];
__device__ float  g_mag1[(size_t)BB*NH];
__device__ float  g_ph1 [(size_t)BB*NH];
__device__ float  g_us  [(size_t)2*BB*64*HH];   // U scratch per CTA
__device__ float2 g_m2  [(size_t)LL*HSQ];   // pre-split Wq@Wk^T
__device__ float2 g_wvm2[(size_t)LL*HSQ];   // pre-split Wvm
__device__ float2 g_wvp2[(size_t)LL*HSQ];   // pre-split Wvp
__device__ float  g_u[LL*HH];
__device__ float  g_v[LL*HH];
__device__ float  g_c[LL];

// ---------------- helpers ----------------
__device__ __forceinline__ void splitT(float x, uint32_t& hi, uint32_t& lo) {
    uint32_t h = __float_as_uint(x) & 0xffffe000u;
    hi = h;
    lo = __float_as_uint(x - __uint_as_float(h));
}
__device__ __forceinline__ void mma8(float* c, const uint32_t* a, uint32_t b0, uint32_t b1) {
    asm volatile("mma.sync.aligned.m16n8k8.row.col.f32.tf32.tf32.f32 "
        "{%0,%1,%2,%3}, {%4,%5,%6,%7}, {%8,%9}, {%0,%1,%2,%3};"
        : "+f"(c[0]), "+f"(c[1]), "+f"(c[2]), "+f"(c[3])
        : "r"(a[0]), "r"(a[1]), "r"(a[2]), "r"(a[3]), "r"(b0), "r"(b1));
}
__device__ __forceinline__ void mma3x(float* c0, float* c1,
                                      const uint32_t* ah0, const uint32_t* al0,
                                      const uint32_t* ah1, const uint32_t* al1,
                                      uint32_t bh0, uint32_t bh1, uint32_t bl0, uint32_t bl1) {
    mma8(c0, ah0, bh0, bh1);
    mma8(c1, ah1, bh0, bh1);
    mma8(c0, ah0, bl0, bl1);
    mma8(c1, ah1, bl0, bl1);
    mma8(c0, al0, bh0, bh1);
    mma8(c1, al1, bh0, bh1);
}
// A fragments from smem (stride ASTR)
__device__ __forceinline__ void loadA(const float* SA_, int wrm, int k0, int gid, int tig,
                                      uint32_t ah[2][4], uint32_t al[2][4]) {
#pragma unroll
    for (int mt = 0; mt < 2; mt++) {
        int rb = wrm + mt*16;
        splitT(SA_[(rb + gid    )*ASTR + k0 + tig    ], ah[mt][0], al[mt][0]);
        splitT(SA_[(rb + gid + 8)*ASTR + k0 + tig    ], ah[mt][1], al[mt][1]);
        splitT(SA_[(rb + gid    )*ASTR + k0 + tig + 4], ah[mt][2], al[mt][2]);
        splitT(SA_[(rb + gid + 8)*ASTR + k0 + tig + 4], ah[mt][3], al[mt][3]);
    }
}
// A fragments from gmem (row stride 128)
__device__ __forceinline__ void loadA_gm(const float* A, int wrm, int k0, int gid, int tig,
                                         uint32_t ah[2][4], uint32_t al[2][4]) {
#pragma unroll
    for (int mt = 0; mt < 2; mt++) {
        int rb = wrm + mt*16;
        splitT(A[(rb + gid    )*HH + k0 + tig    ], ah[mt][0], al[mt][0]);
        splitT(A[(rb + gid + 8)*HH + k0 + tig    ], ah[mt][1], al[mt][1]);
        splitT(A[(rb + gid    )*HH + k0 + tig + 4], ah[mt][2], al[mt][2]);
        splitT(A[(rb + gid + 8)*HH + k0 + tig + 4], ah[mt][3], al[mt][3]);
    }
}
__device__ __forceinline__ void zacc(float a[2][4][4]) {
#pragma unroll
    for (int i = 0; i < 2; i++)
#pragma unroll
        for (int j = 0; j < 4; j++)
#pragma unroll
            for (int q = 0; q < 4; q++) a[i][j][q] = 0.f;
}

// A(smem) x B^T(smem rows): B[k][n] = Bf[n][k], n up to 127
__device__ __forceinline__ void gemm_bt(const float* SA_, const float* Bf,
                                        int wrm, int wrn, int gid, int tig, float acc[2][4][4]) {
    zacc(acc);
#pragma unroll
    for (int k0 = 0; k0 < 128; k0 += 8) {
        uint32_t ah[2][4], al[2][4];
        loadA(SA_, wrm, k0, gid, tig, ah, al);
#pragma unroll
        for (int nt = 0; nt < 4; nt++) {
            int nb = wrn + nt*8;
            uint32_t bh0, bl0, bh1, bl1;
            splitT(Bf[(nb + gid)*ASTR + k0 + tig    ], bh0, bl0);
            splitT(Bf[(nb + gid)*ASTR + k0 + tig + 4], bh1, bl1);
            mma3x(acc[0][nt], acc[1][nt], ah[0], al[0], ah[1], al[1], bh0, bh1, bl0, bl1);
        }
    }
}
// A(smem) x B(smem [k][n] pattern, stride ASTR)
__device__ __forceinline__ void gemm_kn(const float* SA_, const float* Bf,
                                        int wrm, int wrn, int gid, int tig, float acc[2][4][4]) {
    zacc(acc);
#pragma unroll
    for (int k0 = 0; k0 < 128; k0 += 8) {
        uint32_t ah[2][4], al[2][4];
        loadA(SA_, wrm, k0, gid, tig, ah, al);
#pragma unroll
        for (int nt = 0; nt < 4; nt++) {
            int nb = wrn + nt*8;
            uint32_t bh0, bl0, bh1, bl1;
            splitT(Bf[(k0 + tig    )*ASTR + nb + gid], bh0, bl0);
            splitT(Bf[(k0 + tig + 4)*ASTR + nb + gid], bh1, bl1);
            mma3x(acc[0][nt], acc[1][nt], ah[0], al[0], ah[1], al[1], bh0, bh1, bl0, bl1);
        }
    }
}
// A(smem) x B(gmem fp32 [k][n] stride 128, in-loop split)
__device__ __forceinline__ void gemm_gf(const float* SA_, const float* Bf,
                                        int wrm, int wrn, int gid, int tig, float acc[2][4][4]) {
    zacc(acc);
#pragma unroll
    for (int k0 = 0; k0 < 128; k0 += 8) {
        uint32_t ah[2][4], al[2][4];
        loadA(SA_, wrm, k0, gid, tig, ah, al);
#pragma unroll
        for (int nt = 0; nt < 4; nt++) {
            int nb = wrn + nt*8;
            uint32_t bh0, bl0, bh1, bl1;
            splitT(__ldg(&Bf[(k0 + tig    )*HH + nb + gid]), bh0, bl0);
            splitT(__ldg(&Bf[(k0 + tig + 4)*HH + nb + gid]), bh1, bl1);
            mma3x(acc[0][nt], acc[1][nt], ah[0], al[0], ah[1], al[1], bh0, bh1, bl0, bl1);
        }
    }
}
// A(smem) x B(gmem pre-split float2 [k][n] stride 128)
__device__ __forceinline__ void gemm_gw(const float* SA_, const float2* B2,
                                        int wrm, int wrn, int gid, int tig, float acc[2][4][4]) {
    zacc(acc);
#pragma unroll
    for (int k0 = 0; k0 < 128; k0 += 8) {
        uint32_t ah[2][4], al[2][4];
        loadA(SA_, wrm, k0, gid, tig, ah, al);
#pragma unroll
        for (int nt = 0; nt < 4; nt++) {
            int nb = wrn + nt*8;
            float2 b0 = __ldg(&B2[(k0 + tig    )*HH + nb + gid]);
            float2 b1 = __ldg(&B2[(k0 + tig + 4)*HH + nb + gid]);
            mma3x(acc[0][nt], acc[1][nt], ah[0], al[0], ah[1], al[1],
                  __float_as_uint(b0.x), __float_as_uint(b1.x),
                  __float_as_uint(b0.y), __float_as_uint(b1.y));
        }
    }
}
// A(gmem fp32 stride 128) x B(gmem pre-split float2 [k][n])
__device__ __forceinline__ void gemm_ag(const float* A, const float2* B2,
                                        int wrm, int wrn, int gid, int tig, float acc[2][4][4]) {
    zacc(acc);
#pragma unroll
    for (int k0 = 0; k0 < 128; k0 += 8) {
        uint32_t ah[2][4], al[2][4];
        loadA_gm(A, wrm, k0, gid, tig, ah, al);
#pragma unroll
        for (int nt = 0; nt < 4; nt++) {
            int nb = wrn + nt*8;
            float2 b0 = __ldg(&B2[(k0 + tig    )*HH + nb + gid]);
            float2 b1 = __ldg(&B2[(k0 + tig + 4)*HH + nb + gid]);
            mma3x(acc[0][nt], acc[1][nt], ah[0], al[0], ah[1], al[1],
                  __float_as_uint(b0.x), __float_as_uint(b1.x),
                  __float_as_uint(b0.y), __float_as_uint(b1.y));
        }
    }
}

// ---------------- K0: complex embedding ----------------
__global__ void k_embed(const float* __restrict__ at, const float* __restrict__ sph,
                        const float* __restrict__ Wm, const float* __restrict__ bm,
                        const float* __restrict__ Wp, const float* __restrict__ bp)
{
    int b = blockIdx.x, t = threadIdx.x;
    __shared__ float sx[NN][20];
    for (int i = t; i < NN*DIN; i += blockDim.x) {
        int n = i / DIN, d = i % DIN;
        sx[n][d] = (d < INDIM) ? at[((size_t)b*NN + n)*INDIM + d]
                               : sph[((size_t)b*NN + n)*3 + (d - INDIM)];
    }
    __syncthreads();
    float wm[DIN], wp[DIN];
#pragma unroll
    for (int d = 0; d < DIN; d++) { wm[d] = Wm[d*HH + t]; wp[d] = Wp[d*HH + t]; }
    float bmv = bm[t], bpv = bp[t];
    size_t base = (size_t)b*NH;
    for (int n = 0; n < NN; n++) {
        float am = bmv, ap = bpv;
#pragma unroll
        for (int d = 0; d < DIN; d++) { float x = sx[n][d]; am = fmaf(x, wm[d], am); ap = fmaf(x, wp[d], ap); }
        g_mag0[base + (size_t)n*HH + t] = am;
        g_ph0 [base + (size_t)n*HH + t] = ap;
    }
}

// ---------------- prep kernels ----------------
__global__ void k_prep_m(const float* __restrict__ Wq, const float* __restrict__ Wk)
{
    __shared__ float sq[32][129], sk[32][129];
    int l = blockIdx.x, bi = blockIdx.y, bj = blockIdx.z;
    const float* q = Wq + (size_t)l*HSQ + bi*32*HH;
    const float* k = Wk + (size_t)l*HSQ + bj*32*HH;
    int tid = threadIdx.x;
    for (int i = tid; i < 32*128; i += 256) {
        sq[i >> 7][i & 127] = q[(i >> 7)*HH + (i & 127)];
        sk[i >> 7][i & 127] = k[(i >> 7)*HH + (i & 127)];
    }
    __syncthreads();
    int i = tid >> 3, j0 = (tid & 7) * 4;
    for (int jj = 0; jj < 4; jj++) {
        int j = j0 + jj;
        float s = 0.f;
        for (int n = 0; n < 128; n++) s = fmaf(sq[i][n], sk[j][n], s);
        float h = __uint_as_float(__float_as_uint(s) & 0xffffe000u);
        g_m2[(size_t)l*HSQ + (size_t)(bi*32 + i)*HH + bj*32 + j] = make_float2(h, s - h);
    }
}
__global__ void k_prep_uv(const float* __restrict__ Wq, const float* __restrict__ Wk,
                          const float* __restrict__ bqv, const float* __restrict__ bkv)
{
    int l = blockIdx.x, t = threadIdx.x;
    float su = 0.f, sv = 0.f;
    for (int n = 0; n < HH; n++) {
        su = fmaf(Wq[(size_t)l*HSQ + (size_t)t*HH + n], bkv[l*HH + n], su);
        sv = fmaf(Wk[(size_t)l*HSQ + (size_t)t*HH + n], bqv[l*HH + n], sv);
    }
    g_u[l*HH + t] = su;
    g_v[l*HH + t] = sv;
    if (t == 0) {
        float c = 0.f;
        for (int n = 0; n < HH; n++) c = fmaf(bqv[l*HH + n], bkv[l*HH + n], c);
        g_c[l] = c;
    }
}
__global__ void k_wsplit2(const float* __restrict__ Wvm, const float* __restrict__ Wvp)
{
    int m = blockIdx.x;
    int l = m >> 1;
    const float* W = ((m & 1) ? Wvp : Wvm) + (size_t)l*HSQ;
    float2* O = ((m & 1) ? g_wvp2 : g_wvm2) + (size_t)l*HSQ;
    for (int i = threadIdx.x; i < HSQ; i += blockDim.x) {
        float w = W[i];
        float h = __uint_as_float(__float_as_uint(w) & 0xffffe000u);
        O[i] = make_float2(h, w - h);
    }
}

// ---------------- per-layer kernel: one CTA = 64 rows of one molecule ----------------
__global__ __launch_bounds__(256, 2) void k_layer(
    int l,
    const float* __restrict__ srcM, const float* __restrict__ srcP,
    float* __restrict__ dstM, float* __restrict__ dstP,
    const int* __restrict__ ei, const float* __restrict__ ea,
    const float* __restrict__ We, const float* __restrict__ be,
    const float* __restrict__ ds,
    const float* __restrict__ lng, const float* __restrict__ lnb,
    const float* __restrict__ bvm, const float* __restrict__ bvp)
{
    extern __shared__ float sm[];
    float* SM = sm;                 // full mag [128][ASTR]
    float* SS = sm + 128*ASTR;      // t / scores / probs / V / new_mag [64][ASTR]
    __shared__ float sru[NN], srv[NN];

    int cta = blockIdx.x;
    int b = cta >> 1, h = cta & 1;
    int R0 = h * 64;
    int tid = threadIdx.x;
    int wid = tid >> 5, lane = tid & 31;
    int gid = lane >> 2, tig = lane & 3;
    int wrm = (wid & 1) * 32, wrn = (wid >> 1) * 32;
    size_t base = (size_t)b*NH;
    float* up = g_us + (size_t)cta * (64*HH);
    const float scale = 0.08838834764831845f;
    float cL = __ldg(&g_c[l]);
    float acc[2][4][4];

    // ---- load full mag ----
#pragma unroll
    for (int it = 0; it < 16; it++) {
        int idx = tid + 256*it;
        int r = idx >> 5, c = (idx & 31) * 4;
        *(float4*)(SM + r*ASTR + c) = *(const float4*)(srcM + base + (size_t)r*HH + c);
    }
    __syncthreads();

    // ---- ru/rv for all 128 rows (2 threads/row) ----
    {
        int row = tid >> 1, half = tid & 1;
        const float* uu = g_u + l*HH + 64*half;
        const float* vv = g_v + l*HH + 64*half;
        const float* rowp = SM + row*ASTR + 64*half;
        float pu = 0.f, pv = 0.f;
#pragma unroll
        for (int j = 0; j < 64; j++) {
            float mv = rowp[j];
            pu = fmaf(mv, __ldg(uu + j), pu);
            pv = fmaf(mv, __ldg(vv + j), pv);
        }
        pu += __shfl_xor_sync(0xffffffffu, pu, 1);
        pv += __shfl_xor_sync(0xffffffffu, pv, 1);
        if (half == 0) { sru[row] = pu; srv[row] = pv; }
    }
    __syncthreads();

    // ---- phase 2: t = mag_own @ M -> SS ----
    gemm_gw(SM + R0*ASTR, g_m2 + (size_t)l*HSQ, wrm, wrn, gid, tig, acc);
#pragma unroll
    for (int mt = 0; mt < 2; mt++) {
        int r0 = wrm + mt*16 + gid;
#pragma unroll
        for (int nt = 0; nt < 4; nt++) {
            int c = wrn + nt*8 + 2*tig;
            *(float2*)(SS + r0*ASTR + c)     = make_float2(acc[mt][nt][0], acc[mt][nt][1]);
            *(float2*)(SS + (r0+8)*ASTR + c) = make_float2(acc[mt][nt][2], acc[mt][nt][3]);
        }
    }
    __syncthreads();

    // ---- phase 3: scores = (t @ mag_full^T + ru + rv + c)*scale, in-place SS ----
    gemm_bt(SS, SM, wrm, wrn, gid, tig, acc);
    __syncthreads();
#pragma unroll
    for (int mt = 0; mt < 2; mt++) {
        int r0 = wrm + mt*16 + gid, r1 = r0 + 8;
#pragma unroll
        for (int nt = 0; nt < 4; nt++) {
            int c = wrn + nt*8 + 2*tig;
            float rv0 = srv[c], rv1 = srv[c + 1];
            float ru0 = sru[R0 + r0], ru1 = sru[R0 + r1];
            *(float2*)(SS + r0*ASTR + c) = make_float2((acc[mt][nt][0] + ru0 + rv0 + cL) * scale,
                                                       (acc[mt][nt][1] + ru0 + rv1 + cL) * scale);
            *(float2*)(SS + r1*ASTR + c) = make_float2((acc[mt][nt][2] + ru1 + rv0 + cL) * scale,
                                                       (acc[mt][nt][3] + ru1 + rv1 + cL) * scale);
        }
    }
    __syncthreads();

    // ---- edge bias scatter (own rows only) ----
    {
        float w0 = We[l*4+0], w1 = We[l*4+1], w2 = We[l*4+2], w3 = We[l*4+3];
        float beL = be[l], dsL = ds[l];
        for (int e = tid; e < EE; e += 256) {
            int i0 = ei[(size_t)b*2*EE + e];
            int j0 = ei[(size_t)b*2*EE + EE + e];
            if ((unsigned)(i0 - R0) < 64u) {
                const float* a = ea + ((size_t)b*EE + e)*EDIM;
                float v = fmaf(a[0], w0, fmaf(a[1], w1, fmaf(a[2], w2, fmaf(a[3], w3, beL)))) + dsL*a[0];
                atomicAdd(&SS[(i0 - R0)*ASTR + j0], v);
            }
        }
    }
    __syncthreads();

    // ---- softmax rows of SS (4 threads/row, 64 rows) ----
    {
        int row = tid >> 2, qtr = tid & 3;
        float* rp = SS + row*ASTR + 32*qtr;
        float m = -1e30f;
#pragma unroll
        for (int j = 0; j < 8; j++) {
            float4 v = *(const float4*)(rp + 4*j);
            m = fmaxf(m, fmaxf(fmaxf(v.x, v.y), fmaxf(v.z, v.w)));
        }
        m = fmaxf(m, __shfl_xor_sync(0xffffffffu, m, 1));
        m = fmaxf(m, __shfl_xor_sync(0xffffffffu, m, 2));
        float s = 0.f;
#pragma unroll
        for (int j = 0; j < 8; j++) {
            float4 v = *(float4*)(rp + 4*j);
            v.x = __expf(v.x - m); v.y = __expf(v.y - m);
            v.z = __expf(v.z - m); v.w = __expf(v.w - m);
            s += v.x + v.y + v.z + v.w;
            *(float4*)(rp + 4*j) = v;
        }
        s += __shfl_xor_sync(0xffffffffu, s, 1);
        s += __shfl_xor_sync(0xffffffffu, s, 2);
        float inv = 1.f / s;
#pragma unroll
        for (int j = 0; j < 8; j++) {
            float4 v = *(float4*)(rp + 4*j);
            v.x *= inv; v.y *= inv; v.z *= inv; v.w *= inv;
            *(float4*)(rp + 4*j) = v;
        }
    }
    __syncthreads();

    // ---- phase 5: U = P @ mag_full -> gmem scratch ----
    gemm_kn(SS, SM, wrm, wrn, gid, tig, acc);
#pragma unroll
    for (int mt = 0; mt < 2; mt++) {
        int r0 = wrm + mt*16 + gid;
#pragma unroll
        for (int nt = 0; nt < 4; nt++) {
            int c = wrn + nt*8 + 2*tig;
            *(float2*)(up + r0*HH + c)     = make_float2(acc[mt][nt][0], acc[mt][nt][1]);
            *(float2*)(up + (r0+8)*HH + c) = make_float2(acc[mt][nt][2], acc[mt][nt][3]);
        }
    }

    // ---- phase 7: V = P @ ph_full(gmem) ----
    gemm_gf(SS, srcP + base, wrm, wrn, gid, tig, acc);
    __syncthreads();   // all reads of P (SS) done; U stores ordered before this barrier
    // V -> SS
#pragma unroll
    for (int mt = 0; mt < 2; mt++) {
        int r0 = wrm + mt*16 + gid;
#pragma unroll
        for (int nt = 0; nt < 4; nt++) {
            int c = wrn + nt*8 + 2*tig;
            *(float2*)(SS + r0*ASTR + c)     = make_float2(acc[mt][nt][0], acc[mt][nt][1]);
            *(float2*)(SS + (r0+8)*ASTR + c) = make_float2(acc[mt][nt][2], acc[mt][nt][3]);
        }
    }
    __syncthreads();

    // ---- phase 8: new_ph_own = V @ Wvp + bvp + ph_own -> dstP ----
    gemm_gw(SS, g_wvp2 + (size_t)l*HSQ, wrm, wrn, gid, tig, acc);
#pragma unroll
    for (int mt = 0; mt < 2; mt++) {
        int r0 = wrm + mt*16 + gid, r1 = r0 + 8;
#pragma unroll
        for (int nt = 0; nt < 4; nt++) {
            int c = wrn + nt*8 + 2*tig;
            float bv0 = __ldg(bvp + l*HH + c), bv1 = __ldg(bvp + l*HH + c + 1);
            float2 p0 = *(const float2*)(srcP + base + (size_t)(R0 + r0)*HH + c);
            float2 p1 = *(const float2*)(srcP + base + (size_t)(R0 + r1)*HH + c);
            p0.x += acc[mt][nt][0] + bv0; p0.y += acc[mt][nt][1] + bv1;
            p1.x += acc[mt][nt][2] + bv0; p1.y += acc[mt][nt][3] + bv1;
            *(float2*)(dstP + base + (size_t)(R0 + r0)*HH + c) = p0;
            *(float2*)(dstP + base + (size_t)(R0 + r1)*HH + c) = p1;
        }
    }
    __syncthreads();   // all V reads (SS) done

    // ---- phase 6: new_mag_own = U(scratch) @ Wvm + bvm + mag_own -> SS ----
    gemm_ag(up, g_wvm2 + (size_t)l*HSQ, wrm, wrn, gid, tig, acc);
#pragma unroll
    for (int mt = 0; mt < 2; mt++) {
        int r0 = wrm + mt*16 + gid, r1 = r0 + 8;
#pragma unroll
        for (int nt = 0; nt < 4; nt++) {
            int c = wrn + nt*8 + 2*tig;
            float bv0 = __ldg(bvm + l*HH + c), bv1 = __ldg(bvm + l*HH + c + 1);
            float m00 = SM[(R0 + r0)*ASTR + c],     m01 = SM[(R0 + r0)*ASTR + c + 1];
            float m10 = SM[(R0 + r1)*ASTR + c],     m11 = SM[(R0 + r1)*ASTR + c + 1];
            *(float2*)(SS + r0*ASTR + c) = make_float2(acc[mt][nt][0] + bv0 + m00,
                                                       acc[mt][nt][1] + bv1 + m01);
            *(float2*)(SS + r1*ASTR + c) = make_float2(acc[mt][nt][2] + bv0 + m10,
                                                       acc[mt][nt][3] + bv1 + m11);
        }
    }
    __syncthreads();

    // ---- LayerNorm rows of SS -> dstM ----
    {
        int row = tid >> 2, qtr = tid & 3;
        float* rp = SS + row*ASTR + 32*qtr;
        float su = 0.f;
#pragma unroll
        for (int j = 0; j < 8; j++) {
            float4 v = *(const float4*)(rp + 4*j);
            su += v.x + v.y + v.z + v.w;
        }
        su += __shfl_xor_sync(0xffffffffu, su, 1);
        su += __shfl_xor_sync(0xffffffffu, su, 2);
        float mu = su * (1.f/128.f);
        float var = 0.f;
#pragma unroll
        for (int j = 0; j < 8; j++) {
            float4 v = *(const float4*)(rp + 4*j);
            float d0 = v.x - mu, d1 = v.y - mu, d2 = v.z - mu, d3 = v.w - mu;
            var = fmaf(d0, d0, var); var = fmaf(d1, d1, var);
            var = fmaf(d2, d2, var); var = fmaf(d3, d3, var);
        }
        var += __shfl_xor_sync(0xffffffffu, var, 1);
        var += __shfl_xor_sync(0xffffffffu, var, 2);
        float rs = rsqrtf(var * (1.f/128.f) + 1e-5f);
        const float* gp  = lng + l*HH + 32*qtr;
        const float* bp2 = lnb + l*HH + 32*qtr;
        float* op = dstM + base + (size_t)(R0 + row)*HH + 32*qtr;
#pragma unroll
        for (int j = 0; j < 8; j++) {
            float4 v = *(const float4*)(rp + 4*j);
            float4 g = *(const float4*)(gp + 4*j);
            float4 be2 = *(const float4*)(bp2 + 4*j);
            v.x = fmaf(g.x, (v.x - mu)*rs, be2.x);
            v.y = fmaf(g.y, (v.y - mu)*rs, be2.y);
            v.z = fmaf(g.z, (v.z - mu)*rs, be2.z);
            v.w = fmaf(g.w, (v.w - mu)*rs, be2.w);
            *(float4*)(op + 4*j) = v;
        }
    }
}

// ---------------- K3: head ----------------
__global__ void k_head(const float* __restrict__ rpW, const float* __restrict__ rpb,
                       const float* __restrict__ h1W, const float* __restrict__ h1b,
                       const float* __restrict__ h2W, const float* __restrict__ h2b,
                       float* __restrict__ out)
{
    int b = blockIdx.x, t = threadIdx.x;
    __shared__ float sS[2*HH];
    __shared__ float sp[2*HH];
    __shared__ float sr[HH];
    size_t base = (size_t)b*NH;

    float ac = 0.f, as = 0.f;
    for (int n = 0; n < NN; n++) {
        float m = g_mag0[base + (size_t)n*HH + t];
        float p = g_ph0 [base + (size_t)n*HH + t];
        float si, co;
        sincosf(p, &si, &co);
        ac = fmaf(m, co, ac);
        as = fmaf(m, si, as);
    }
    sS[t] = ac; sS[HH + t] = as;
    __syncthreads();

    float d = 0.f;
    for (int c = 0; c < 2*HH; c++) d = fmaf(sS[c], rpW[(size_t)c*HH + t], d);
    float sumr = d + 128.f * rpb[t];
    sp[t]      = sumr * (1.f/128.f);
    sp[HH + t] = sumr;
    __syncthreads();

    float hv = h1b[t];
    for (int c = 0; c < 2*HH; c++) hv = fmaf(sp[c], h1W[(size_t)c*HH + t], hv);
    hv = hv / (1.f + expf(-hv));
    sr[t] = hv * h2W[t];
    __syncthreads();

    for (int s = 64; s >= 1; s >>= 1) {
        if (t < s) sr[t] += sr[t + s];
        __syncthreads();
    }
    if (t == 0) out[b] = sr[0] + h2b[0];
}

// ---------------- launch ----------------
extern "C" void kernel_launch(void* const* d_in, const int* in_sizes, int n_in,
                              void* d_out, int out_size)
{
    const float* at   = (const float*)d_in[0];
    const float* sph  = (const float*)d_in[1];
    const int*   ei   = (const int*)  d_in[2];
    const float* ea   = (const float*)d_in[3];
    const float* Wm   = (const float*)d_in[4];
    const float* bm   = (const float*)d_in[5];
    const float* Wp   = (const float*)d_in[6];
    const float* bp   = (const float*)d_in[7];
    const float* Wq   = (const float*)d_in[8];
    const float* bq   = (const float*)d_in[9];
    const float* Wk   = (const float*)d_in[10];
    const float* bk   = (const float*)d_in[11];
    const float* Wvm  = (const float*)d_in[12];
    const float* bvm  = (const float*)d_in[13];
    const float* Wvp  = (const float*)d_in[14];
    const float* bvp  = (const float*)d_in[15];
    const float* We   = (const float*)d_in[16];
    const float* be   = (const float*)d_in[17];
    const float* ds   = (const float*)d_in[18];
    const float* lng  = (const float*)d_in[19];
    const float* lnb  = (const float*)d_in[20];
    const float* rpW  = (const float*)d_in[21];
    const float* rpb  = (const float*)d_in[22];
    const float* h1W  = (const float*)d_in[23];
    const float* h1b  = (const float*)d_in[24];
    const float* h2W  = (const float*)d_in[25];
    const float* h2b  = (const float*)d_in[26];
    float* out = (float*)d_out;

    void *m0, *m1, *p0, *p1;
    cudaGetSymbolAddress(&m0, g_mag0);
    cudaGetSymbolAddress(&m1, g_mag1);
    cudaGetSymbolAddress(&p0, g_ph0);
    cudaGetSymbolAddress(&p1, g_ph1);

    size_t layer_smem = (size_t)(128 + 64) * ASTR * sizeof(float);   // 101376
    cudaFuncSetAttribute(k_layer, cudaFuncAttributeMaxDynamicSharedMemorySize, (int)layer_smem);

    k_embed<<<BB, 128>>>(at, sph, Wm, bm, Wp, bp);
    k_prep_m<<<dim3(LL, 4, 4), 256>>>(Wq, Wk);
    k_prep_uv<<<LL, 128>>>(Wq, Wk, bq, bk);
    k_wsplit2<<<2*LL, 256>>>(Wvm, Wvp);

    for (int l = 0; l < LL; l++) {
        const float* sM = (const float*)((l & 1) ? m1 : m0);
        const float* sP = (const float*)((l & 1) ? p1 : p0);
        float* dM = (float*)((l & 1) ? m0 : m1);
        float* dP = (float*)((l & 1) ? p0 : p1);
        k_layer<<<2*BB, 256, layer_smem>>>(l, sM, sP, dM, dP,
                                           ei, ea, We, be, ds, lng, lnb, bvm, bvp);
    }

    k_head<<<BB, 128>>>(rpW, rpb, h1W, h1b, h2W, h2b, out);
}

// round 16
// speedup vs baseline: 1.3006x; 1.3006x over previous
#include <cuda_runtime.h>
#include <math.h>
#include <stdint.h>

#define BB   1024
#define NN   128
#define EE   1024
#define HH   128
#define LL   4
#define INDIM 16
#define DIN  19
#define EDIM 4
#define NH   (NN*HH)      // 16384
#define HSQ  (HH*HH)      // 16384
#define ASTR 132          // fp32 stride for S2
#define F2S  132          // float2 stride for S1 (pre-split)

// ---------------- device scratch ----------------
__device__ float  g_mag[(size_t)BB*NH];
__device__ float  g_ph [(size_t)BB*NH];
__device__ float  g_us [(size_t)BB*NH];     // U scratch (per molecule)
__device__ float2 g_m2  [(size_t)LL*HSQ];   // pre-split Wq@Wk^T
__device__ float2 g_wvm2[(size_t)LL*HSQ];   // pre-split Wvm
__device__ float2 g_wvp2[(size_t)LL*HSQ];   // pre-split Wvp
__device__ float  g_u[LL*HH];
__device__ float  g_v[LL*HH];
__device__ float  g_c[LL];

// ---------------- helpers ----------------
__device__ __forceinline__ void splitT(float x, uint32_t& hi, uint32_t& lo) {
    uint32_t h = __float_as_uint(x) & 0xffffe000u;
    hi = h;
    lo = __float_as_uint(x - __uint_as_float(h));
}
__device__ __forceinline__ float2 split2(float x) {
    float h = __uint_as_float(__float_as_uint(x) & 0xffffe000u);
    return make_float2(h, x - h);
}
__device__ __forceinline__ void mma8(float* c, const uint32_t* a, uint32_t b0, uint32_t b1) {
    asm volatile("mma.sync.aligned.m16n8k8.row.col.f32.tf32.tf32.f32 "
        "{%0,%1,%2,%3}, {%4,%5,%6,%7}, {%8,%9}, {%0,%1,%2,%3};"
        : "+f"(c[0]), "+f"(c[1]), "+f"(c[2]), "+f"(c[3])
        : "r"(a[0]), "r"(a[1]), "r"(a[2]), "r"(a[3]), "r"(b0), "r"(b1));
}
__device__ __forceinline__ void mma3x(float* c0, float* c1,
                                      const uint32_t* ah0, const uint32_t* al0,
                                      const uint32_t* ah1, const uint32_t* al1,
                                      uint32_t bh0, uint32_t bh1, uint32_t bl0, uint32_t bl1) {
    mma8(c0, ah0, bh0, bh1);
    mma8(c1, ah1, bh0, bh1);
    mma8(c0, ah0, bl0, bl1);
    mma8(c1, ah1, bl0, bl1);
    mma8(c0, al0, bh0, bh1);
    mma8(c1, al1, bh0, bh1);
}
__device__ __forceinline__ void zacc(float a[2][4][4]) {
#pragma unroll
    for (int i = 0; i < 2; i++)
#pragma unroll
        for (int j = 0; j < 4; j++)
#pragma unroll
            for (int q = 0; q < 4; q++) a[i][j][q] = 0.f;
}
// A fragments: fp32 smem, in-loop split
__device__ __forceinline__ void loadA(const float* SA_, int wrm, int k0, int gid, int tig,
                                      uint32_t ah[2][4], uint32_t al[2][4]) {
#pragma unroll
    for (int mt = 0; mt < 2; mt++) {
        int rb = wrm + mt*16;
        splitT(SA_[(rb + gid    )*ASTR + k0 + tig    ], ah[mt][0], al[mt][0]);
        splitT(SA_[(rb + gid + 8)*ASTR + k0 + tig    ], ah[mt][1], al[mt][1]);
        splitT(SA_[(rb + gid    )*ASTR + k0 + tig + 4], ah[mt][2], al[mt][2]);
        splitT(SA_[(rb + gid + 8)*ASTR + k0 + tig + 4], ah[mt][3], al[mt][3]);
    }
}
// A fragments: pre-split float2 smem (LDS.64)
__device__ __forceinline__ void loadA2(const float2* S1f2, int wrm, int k0, int gid, int tig,
                                       uint32_t ah[2][4], uint32_t al[2][4]) {
#pragma unroll
    for (int mt = 0; mt < 2; mt++) {
        int rb = wrm + mt*16;
        float2 v0 = S1f2[(rb + gid    )*F2S + k0 + tig    ];
        float2 v1 = S1f2[(rb + gid + 8)*F2S + k0 + tig    ];
        float2 v2 = S1f2[(rb + gid    )*F2S + k0 + tig + 4];
        float2 v3 = S1f2[(rb + gid + 8)*F2S + k0 + tig + 4];
        ah[mt][0] = __float_as_uint(v0.x); al[mt][0] = __float_as_uint(v0.y);
        ah[mt][1] = __float_as_uint(v1.x); al[mt][1] = __float_as_uint(v1.y);
        ah[mt][2] = __float_as_uint(v2.x); al[mt][2] = __float_as_uint(v2.y);
        ah[mt][3] = __float_as_uint(v3.x); al[mt][3] = __float_as_uint(v3.y);
    }
}
// A fragments: gmem fp32 (row stride 128), COHERENT loads (data written this launch)
__device__ __forceinline__ void loadA_gm(const float* A, int wrm, int k0, int gid, int tig,
                                         uint32_t ah[2][4], uint32_t al[2][4]) {
#pragma unroll
    for (int mt = 0; mt < 2; mt++) {
        int rb = wrm + mt*16;
        splitT(A[(rb + gid    )*HH + k0 + tig    ], ah[mt][0], al[mt][0]);
        splitT(A[(rb + gid + 8)*HH + k0 + tig    ], ah[mt][1], al[mt][1]);
        splitT(A[(rb + gid    )*HH + k0 + tig + 4], ah[mt][2], al[mt][2]);
        splitT(A[(rb + gid + 8)*HH + k0 + tig + 4], ah[mt][3], al[mt][3]);
    }
}

// phase 2: A = pre-split S1, B = gmem pre-split float2 [k][n] (launch-constant, __ldg ok)
__device__ __forceinline__ void gemm_p2(const float2* S1f2, const float2* B2,
                                        int wrm, int wrn, int gid, int tig, float acc[2][4][4]) {
    zacc(acc);
#pragma unroll
    for (int k0 = 0; k0 < 128; k0 += 8) {
        uint32_t ah[2][4], al[2][4];
        loadA2(S1f2, wrm, k0, gid, tig, ah, al);
#pragma unroll
        for (int nt = 0; nt < 4; nt++) {
            int nb = wrn + nt*8;
            float2 b0 = __ldg(&B2[(k0 + tig    )*HH + nb + gid]);
            float2 b1 = __ldg(&B2[(k0 + tig + 4)*HH + nb + gid]);
            mma3x(acc[0][nt], acc[1][nt], ah[0], al[0], ah[1], al[1],
                  __float_as_uint(b0.x), __float_as_uint(b1.x),
                  __float_as_uint(b0.y), __float_as_uint(b1.y));
        }
    }
}
// phase 3: A = fp32 smem (t), B^T = pre-split S1 rows (B[k][n] = S1[n][k])
__device__ __forceinline__ void gemm_p3(const float* SA_, const float2* S1f2,
                                        int wrm, int wrn, int gid, int tig, float acc[2][4][4]) {
    zacc(acc);
#pragma unroll
    for (int k0 = 0; k0 < 128; k0 += 8) {
        uint32_t ah[2][4], al[2][4];
        loadA(SA_, wrm, k0, gid, tig, ah, al);
#pragma unroll
        for (int nt = 0; nt < 4; nt++) {
            int nb = wrn + nt*8;
            float2 b0 = S1f2[(nb + gid)*F2S + k0 + tig    ];
            float2 b1 = S1f2[(nb + gid)*F2S + k0 + tig + 4];
            mma3x(acc[0][nt], acc[1][nt], ah[0], al[0], ah[1], al[1],
                  __float_as_uint(b0.x), __float_as_uint(b1.x),
                  __float_as_uint(b0.y), __float_as_uint(b1.y));
        }
    }
}
// dual: A = fp32 smem (P), B1 = pre-split S1 kn-pattern, B2 = gmem fp32 ph
// ph is written EARLIER IN THIS LAUNCH (previous layer) -> MUST use coherent loads
__device__ __forceinline__ void gemm_du(const float* SA_, const float2* S1f2, const float* B2f,
                                        int wrm, int wrn, int gid, int tig,
                                        float accU[2][4][4], float accV[2][4][4]) {
    zacc(accU); zacc(accV);
#pragma unroll
    for (int k0 = 0; k0 < 128; k0 += 8) {
        uint32_t ah[2][4], al[2][4];
        loadA(SA_, wrm, k0, gid, tig, ah, al);
#pragma unroll
        for (int nt = 0; nt < 4; nt++) {
            int nb = wrn + nt*8;
            float2 b0 = S1f2[(k0 + tig    )*F2S + nb + gid];
            float2 b1 = S1f2[(k0 + tig + 4)*F2S + nb + gid];
            mma3x(accU[0][nt], accU[1][nt], ah[0], al[0], ah[1], al[1],
                  __float_as_uint(b0.x), __float_as_uint(b1.x),
                  __float_as_uint(b0.y), __float_as_uint(b1.y));
            uint32_t bh0, bl0, bh1, bl1;
            splitT(B2f[(k0 + tig    )*HH + nb + gid], bh0, bl0);
            splitT(B2f[(k0 + tig + 4)*HH + nb + gid], bh1, bl1);
            mma3x(accV[0][nt], accV[1][nt], ah[0], al[0], ah[1], al[1], bh0, bh1, bl0, bl1);
        }
    }
}
// phase 6: A = gmem fp32 (U scratch, written this launch -> coherent), B = weights (__ldg ok)
__device__ __forceinline__ void gemm_ag(const float* A, const float2* B2,
                                        int wrm, int wrn, int gid, int tig, float acc[2][4][4]) {
    zacc(acc);
#pragma unroll
    for (int k0 = 0; k0 < 128; k0 += 8) {
        uint32_t ah[2][4], al[2][4];
        loadA_gm(A, wrm, k0, gid, tig, ah, al);
#pragma unroll
        for (int nt = 0; nt < 4; nt++) {
            int nb = wrn + nt*8;
            float2 b0 = __ldg(&B2[(k0 + tig    )*HH + nb + gid]);
            float2 b1 = __ldg(&B2[(k0 + tig + 4)*HH + nb + gid]);
            mma3x(acc[0][nt], acc[1][nt], ah[0], al[0], ah[1], al[1],
                  __float_as_uint(b0.x), __float_as_uint(b1.x),
                  __float_as_uint(b0.y), __float_as_uint(b1.y));
        }
    }
}
// phase 8: A = fp32 smem (V), B = weights (__ldg ok)
__device__ __forceinline__ void gemm_gw(const float* SA_, const float2* B2,
                                        int wrm, int wrn, int gid, int tig, float acc[2][4][4]) {
    zacc(acc);
#pragma unroll
    for (int k0 = 0; k0 < 128; k0 += 8) {
        uint32_t ah[2][4], al[2][4];
        loadA(SA_, wrm, k0, gid, tig, ah, al);
#pragma unroll
        for (int nt = 0; nt < 4; nt++) {
            int nb = wrn + nt*8;
            float2 b0 = __ldg(&B2[(k0 + tig    )*HH + nb + gid]);
            float2 b1 = __ldg(&B2[(k0 + tig + 4)*HH + nb + gid]);
            mma3x(acc[0][nt], acc[1][nt], ah[0], al[0], ah[1], al[1],
                  __float_as_uint(b0.x), __float_as_uint(b1.x),
                  __float_as_uint(b0.y), __float_as_uint(b1.y));
        }
    }
}

// ---------------- K0: complex embedding ----------------
__global__ void k_embed(const float* __restrict__ at, const float* __restrict__ sph,
                        const float* __restrict__ Wm, const float* __restrict__ bm,
                        const float* __restrict__ Wp, const float* __restrict__ bp)
{
    int b = blockIdx.x, t = threadIdx.x;
    __shared__ float sx[NN][20];
    for (int i = t; i < NN*DIN; i += blockDim.x) {
        int n = i / DIN, d = i % DIN;
        sx[n][d] = (d < INDIM) ? at[((size_t)b*NN + n)*INDIM + d]
                               : sph[((size_t)b*NN + n)*3 + (d - INDIM)];
    }
    __syncthreads();
    float wm[DIN], wp[DIN];
#pragma unroll
    for (int d = 0; d < DIN; d++) { wm[d] = Wm[d*HH + t]; wp[d] = Wp[d*HH + t]; }
    float bmv = bm[t], bpv = bp[t];
    size_t base = (size_t)b*NH;
    for (int n = 0; n < NN; n++) {
        float am = bmv, ap = bpv;
#pragma unroll
        for (int d = 0; d < DIN; d++) { float x = sx[n][d]; am = fmaf(x, wm[d], am); ap = fmaf(x, wp[d], ap); }
        g_mag[base + (size_t)n*HH + t] = am;
        g_ph [base + (size_t)n*HH + t] = ap;
    }
}

// ---------------- prep kernels ----------------
__global__ void k_prep_m(const float* __restrict__ Wq, const float* __restrict__ Wk)
{
    __shared__ float sq[32][129], sk[32][129];
    int l = blockIdx.x, bi = blockIdx.y, bj = blockIdx.z;
    const float* q = Wq + (size_t)l*HSQ + bi*32*HH;
    const float* k = Wk + (size_t)l*HSQ + bj*32*HH;
    int tid = threadIdx.x;
    for (int i = tid; i < 32*128; i += 256) {
        sq[i >> 7][i & 127] = q[(i >> 7)*HH + (i & 127)];
        sk[i >> 7][i & 127] = k[(i >> 7)*HH + (i & 127)];
    }
    __syncthreads();
    int i = tid >> 3, j0 = (tid & 7) * 4;
    for (int jj = 0; jj < 4; jj++) {
        int j = j0 + jj;
        float s = 0.f;
        for (int n = 0; n < 128; n++) s = fmaf(sq[i][n], sk[j][n], s);
        g_m2[(size_t)l*HSQ + (size_t)(bi*32 + i)*HH + bj*32 + j] = split2(s);
    }
}
__global__ void k_prep_uv(const float* __restrict__ Wq, const float* __restrict__ Wk,
                          const float* __restrict__ bqv, const float* __restrict__ bkv)
{
    int l = blockIdx.x, t = threadIdx.x;
    float su = 0.f, sv = 0.f;
    for (int n = 0; n < HH; n++) {
        su = fmaf(Wq[(size_t)l*HSQ + (size_t)t*HH + n], bkv[l*HH + n], su);
        sv = fmaf(Wk[(size_t)l*HSQ + (size_t)t*HH + n], bqv[l*HH + n], sv);
    }
    g_u[l*HH + t] = su;
    g_v[l*HH + t] = sv;
    if (t == 0) {
        float c = 0.f;
        for (int n = 0; n < HH; n++) c = fmaf(bqv[l*HH + n], bkv[l*HH + n], c);
        g_c[l] = c;
    }
}
__global__ void k_wsplit2(const float* __restrict__ Wvm, const float* __restrict__ Wvp)
{
    int m = blockIdx.x;
    int l = m >> 1;
    const float* W = ((m & 1) ? Wvp : Wvm) + (size_t)l*HSQ;
    float2* O = ((m & 1) ? g_wvp2 : g_wvm2) + (size_t)l*HSQ;
    for (int i = threadIdx.x; i < HSQ; i += blockDim.x)
        O[i] = split2(W[i]);
}

// ---------------- fused layer kernel ----------------
__global__ __launch_bounds__(512) void k_layer(
    const int* __restrict__ ei, const float* __restrict__ ea,
    const float* __restrict__ We, const float* __restrict__ be,
    const float* __restrict__ ds,
    const float* __restrict__ lng, const float* __restrict__ lnb,
    const float* __restrict__ bvm, const float* __restrict__ bvp)
{
    extern __shared__ float sm[];
    float2* S1 = (float2*)sm;            // pre-split mag [128][F2S]
    float*  S2 = sm + 2*NN*F2S;          // fp32 [128][ASTR]: t / scores / probs / V
    __shared__ float sru[NN], srv[NN];

    int b = blockIdx.x, tid = threadIdx.x;
    int wid = tid >> 5, lane = tid & 31;
    int gid = lane >> 2, tig = lane & 3;
    int wrm = (wid & 3) * 32, wrn = (wid >> 2) * 32;
    size_t base = (size_t)b*NH;
    float* php = g_ph + base;
    float* up  = g_us + base;
    const float scale = 0.08838834764831845f;   // 1/sqrt(128)

    // load mag into S1 (pre-split)
#pragma unroll
    for (int it = 0; it < 8; it++) {
        int idx = tid + 512*it;
        int r = idx >> 5, c = (idx & 31) * 4;
        float4 v = *(const float4*)(g_mag + base + (size_t)r*HH + c);
        float2 s0 = split2(v.x), s1 = split2(v.y), s2 = split2(v.z), s3 = split2(v.w);
        *(float4*)(S1 + r*F2S + c)     = make_float4(s0.x, s0.y, s1.x, s1.y);
        *(float4*)(S1 + r*F2S + c + 2) = make_float4(s2.x, s2.y, s3.x, s3.y);
    }
    __syncthreads();

    float acc[2][4][4];
    float accV[2][4][4];

#pragma unroll 1
    for (int l = 0; l < LL; l++) {
        float cL = __ldg(&g_c[l]);

        // ---- ru/rv (reads S1, reconstruct hi+lo) ----
        {
            int row = tid >> 2, qtr = tid & 3;
            const float* uu = g_u + l*HH + 32*qtr;
            const float* vv = g_v + l*HH + 32*qtr;
            const float2* rowp = S1 + row*F2S + 32*qtr;
            float pu = 0.f, pv = 0.f;
#pragma unroll
            for (int j = 0; j < 32; j++) {
                float2 w = rowp[j];
                float mv = w.x + w.y;
                pu = fmaf(mv, __ldg(uu + j), pu);
                pv = fmaf(mv, __ldg(vv + j), pv);
            }
            pu += __shfl_xor_sync(0xffffffffu, pu, 1);
            pu += __shfl_xor_sync(0xffffffffu, pu, 2);
            pv += __shfl_xor_sync(0xffffffffu, pv, 1);
            pv += __shfl_xor_sync(0xffffffffu, pv, 2);
            if (qtr == 0) { sru[row] = pu; srv[row] = pv; }
        }
        __syncthreads();

        // ---- phase 2: t = mag @ M -> S2 ----
        gemm_p2(S1, g_m2 + (size_t)l*HSQ, wrm, wrn, gid, tig, acc);
#pragma unroll
        for (int mt = 0; mt < 2; mt++) {
            int r0 = wrm + mt*16 + gid;
#pragma unroll
            for (int nt = 0; nt < 4; nt++) {
                int c = wrn + nt*8 + 2*tig;
                *(float2*)(S2 + r0*ASTR + c)     = make_float2(acc[mt][nt][0], acc[mt][nt][1]);
                *(float2*)(S2 + (r0+8)*ASTR + c) = make_float2(acc[mt][nt][2], acc[mt][nt][3]);
            }
        }
        __syncthreads();

        // ---- phase 3: scores = (t @ mag^T + ru + rv + c)*scale, in-place S2 ----
        gemm_p3(S2, S1, wrm, wrn, gid, tig, acc);
        __syncthreads();   // all reads of t done before in-place overwrite
#pragma unroll
        for (int mt = 0; mt < 2; mt++) {
            int r0 = wrm + mt*16 + gid, r1 = r0 + 8;
#pragma unroll
            for (int nt = 0; nt < 4; nt++) {
                int c = wrn + nt*8 + 2*tig;
                float rv0 = srv[c], rv1 = srv[c + 1];
                *(float2*)(S2 + r0*ASTR + c) = make_float2((acc[mt][nt][0] + sru[r0] + rv0 + cL) * scale,
                                                           (acc[mt][nt][1] + sru[r0] + rv1 + cL) * scale);
                *(float2*)(S2 + r1*ASTR + c) = make_float2((acc[mt][nt][2] + sru[r1] + rv0 + cL) * scale,
                                                           (acc[mt][nt][3] + sru[r1] + rv1 + cL) * scale);
            }
        }
        __syncthreads();

        // ---- edge bias scatter onto scores (S2) ----
        {
            float w0 = We[l*4+0], w1 = We[l*4+1], w2 = We[l*4+2], w3 = We[l*4+3];
            float beL = be[l], dsL = ds[l];
            for (int e = tid; e < EE; e += 512) {
                int i0 = ei[(size_t)b*2*EE + e];
                int j0 = ei[(size_t)b*2*EE + EE + e];
                const float* a = ea + ((size_t)b*EE + e)*EDIM;
                float v = fmaf(a[0], w0, fmaf(a[1], w1, fmaf(a[2], w2, fmaf(a[3], w3, beL)))) + dsL*a[0];
                atomicAdd(&S2[i0*ASTR + j0], v);
            }
        }
        __syncthreads();

        // ---- phase 4: softmax rows of S2 (4 threads/row) ----
        {
            int row = tid >> 2, qtr = tid & 3;
            float* rp = S2 + row*ASTR + 32*qtr;
            float m = -1e30f;
#pragma unroll
            for (int j = 0; j < 8; j++) {
                float4 v = *(const float4*)(rp + 4*j);
                m = fmaxf(m, fmaxf(fmaxf(v.x, v.y), fmaxf(v.z, v.w)));
            }
            m = fmaxf(m, __shfl_xor_sync(0xffffffffu, m, 1));
            m = fmaxf(m, __shfl_xor_sync(0xffffffffu, m, 2));
            float s = 0.f;
#pragma unroll
            for (int j = 0; j < 8; j++) {
                float4 v = *(float4*)(rp + 4*j);
                v.x = __expf(v.x - m); v.y = __expf(v.y - m);
                v.z = __expf(v.z - m); v.w = __expf(v.w - m);
                s += v.x + v.y + v.z + v.w;
                *(float4*)(rp + 4*j) = v;
            }
            s += __shfl_xor_sync(0xffffffffu, s, 1);
            s += __shfl_xor_sync(0xffffffffu, s, 2);
            float inv = 1.f / s;
#pragma unroll
            for (int j = 0; j < 8; j++) {
                float4 v = *(float4*)(rp + 4*j);
                v.x *= inv; v.y *= inv; v.z *= inv; v.w *= inv;
                *(float4*)(rp + 4*j) = v;
            }
        }
        __syncthreads();

        // ---- phase 5+7: U = P @ mag(S1 presplit), V = P @ ph(gmem, coherent) ----
        gemm_du(S2, S1, php, wrm, wrn, gid, tig, acc, accV);
        // U -> gmem scratch
#pragma unroll
        for (int mt = 0; mt < 2; mt++) {
            int r0 = wrm + mt*16 + gid;
#pragma unroll
            for (int nt = 0; nt < 4; nt++) {
                int c = wrn + nt*8 + 2*tig;
                *(float2*)(up + r0*HH + c)     = make_float2(acc[mt][nt][0], acc[mt][nt][1]);
                *(float2*)(up + (r0+8)*HH + c) = make_float2(acc[mt][nt][2], acc[mt][nt][3]);
            }
        }
        __syncthreads();   // all reads of P (S2) complete; U stores ordered
        // V -> S2
#pragma unroll
        for (int mt = 0; mt < 2; mt++) {
            int r0 = wrm + mt*16 + gid;
#pragma unroll
            for (int nt = 0; nt < 4; nt++) {
                int c = wrn + nt*8 + 2*tig;
                *(float2*)(S2 + r0*ASTR + c)     = make_float2(accV[mt][nt][0], accV[mt][nt][1]);
                *(float2*)(S2 + (r0+8)*ASTR + c) = make_float2(accV[mt][nt][2], accV[mt][nt][3]);
            }
        }
        __syncthreads();

        // ---- phase 6: new_mag = U(scratch) @ Wvm + bvm + mag -> S1 (pre-split RMW) ----
        gemm_ag(up, g_wvm2 + (size_t)l*HSQ, wrm, wrn, gid, tig, acc);
#pragma unroll
        for (int mt = 0; mt < 2; mt++) {
            int r0 = wrm + mt*16 + gid, r1 = r0 + 8;
#pragma unroll
            for (int nt = 0; nt < 4; nt++) {
                int c = wrn + nt*8 + 2*tig;
                float bv0 = __ldg(bvm + l*HH + c), bv1 = __ldg(bvm + l*HH + c + 1);
                float4 o0 = *(float4*)(S1 + r0*F2S + c);   // (hi0,lo0,hi1,lo1)
                float4 o1 = *(float4*)(S1 + r1*F2S + c);
                float x00 = o0.x + o0.y + acc[mt][nt][0] + bv0;
                float x01 = o0.z + o0.w + acc[mt][nt][1] + bv1;
                float x10 = o1.x + o1.y + acc[mt][nt][2] + bv0;
                float x11 = o1.z + o1.w + acc[mt][nt][3] + bv1;
                float2 s00 = split2(x00), s01 = split2(x01);
                float2 s10 = split2(x10), s11 = split2(x11);
                *(float4*)(S1 + r0*F2S + c) = make_float4(s00.x, s00.y, s01.x, s01.y);
                *(float4*)(S1 + r1*F2S + c) = make_float4(s10.x, s10.y, s11.x, s11.y);
            }
        }
        __syncthreads();

        // ---- LayerNorm rows of S1 (4 threads/row, reconstruct + re-split) ----
        {
            int row = tid >> 2, qtr = tid & 3;
            float2* rp = S1 + row*F2S + 32*qtr;
            float xs[32];
            float su = 0.f;
#pragma unroll
            for (int j = 0; j < 32; j++) {
                float2 w = rp[j];
                xs[j] = w.x + w.y;
                su += xs[j];
            }
            su += __shfl_xor_sync(0xffffffffu, su, 1);
            su += __shfl_xor_sync(0xffffffffu, su, 2);
            float mu = su * (1.f/128.f);
            float var = 0.f;
#pragma unroll
            for (int j = 0; j < 32; j++) {
                float d = xs[j] - mu;
                var = fmaf(d, d, var);
            }
            var += __shfl_xor_sync(0xffffffffu, var, 1);
            var += __shfl_xor_sync(0xffffffffu, var, 2);
            float rs = rsqrtf(var * (1.f/128.f) + 1e-5f);
            const float* gp  = lng + l*HH + 32*qtr;
            const float* bp2 = lnb + l*HH + 32*qtr;
#pragma unroll
            for (int j = 0; j < 32; j++) {
                float y = fmaf(__ldg(gp + j), (xs[j] - mu)*rs, __ldg(bp2 + j));
                rp[j] = split2(y);
            }
        }
        __syncthreads();

        // ---- phase 8: new_ph = V @ Wvp + bvp + ph -> gmem ph (in place) ----
        gemm_gw(S2, g_wvp2 + (size_t)l*HSQ, wrm, wrn, gid, tig, acc);
#pragma unroll
        for (int mt = 0; mt < 2; mt++) {
            int r0 = wrm + mt*16 + gid, r1 = r0 + 8;
#pragma unroll
            for (int nt = 0; nt < 4; nt++) {
                int c = wrn + nt*8 + 2*tig;
                float bv0 = __ldg(bvp + l*HH + c), bv1 = __ldg(bvp + l*HH + c + 1);
                float2 o0 = *(float2*)(php + (size_t)r0*HH + c);
                float2 o1 = *(float2*)(php + (size_t)r1*HH + c);
                o0.x += acc[mt][nt][0] + bv0; o0.y += acc[mt][nt][1] + bv1;
                o1.x += acc[mt][nt][2] + bv0; o1.y += acc[mt][nt][3] + bv1;
                *(float2*)(php + (size_t)r0*HH + c) = o0;
                *(float2*)(php + (size_t)r1*HH + c) = o1;
            }
        }
        __syncthreads();
    }

    // write final mag back (reconstruct)
#pragma unroll
    for (int it = 0; it < 8; it++) {
        int idx = tid + 512*it;
        int r = idx >> 5, c = (idx & 31) * 4;
        float4 a = *(const float4*)(S1 + r*F2S + c);
        float4 bq = *(const float4*)(S1 + r*F2S + c + 2);
        *(float4*)(g_mag + base + (size_t)r*HH + c) =
            make_float4(a.x + a.y, a.z + a.w, bq.x + bq.y, bq.z + bq.w);
    }
}

// ---------------- K3: head ----------------
__global__ void k_head(const float* __restrict__ rpW, const float* __restrict__ rpb,
                       const float* __restrict__ h1W, const float* __restrict__ h1b,
                       const float* __restrict__ h2W, const float* __restrict__ h2b,
                       float* __restrict__ out)
{
    int b = blockIdx.x, t = threadIdx.x;
    __shared__ float sS[2*HH];
    __shared__ float sp[2*HH];
    __shared__ float sr[HH];
    size_t base = (size_t)b*NH;

    float ac = 0.f, as = 0.f;
    for (int n = 0; n < NN; n++) {
        float m = g_mag[base + (size_t)n*HH + t];
        float p = g_ph [base + (size_t)n*HH + t];
        float si, co;
        sincosf(p, &si, &co);
        ac = fmaf(m, co, ac);
        as = fmaf(m, si, as);
    }
    sS[t] = ac; sS[HH + t] = as;
    __syncthreads();

    float d = 0.f;
    for (int c = 0; c < 2*HH; c++) d = fmaf(sS[c], rpW[(size_t)c*HH + t], d);
    float sumr = d + 128.f * rpb[t];
    sp[t]      = sumr * (1.f/128.f);
    sp[HH + t] = sumr;
    __syncthreads();

    float hv = h1b[t];
    for (int c = 0; c < 2*HH; c++) hv = fmaf(sp[c], h1W[(size_t)c*HH + t], hv);
    hv = hv / (1.f + expf(-hv));
    sr[t] = hv * h2W[t];
    __syncthreads();

    for (int s = 64; s >= 1; s >>= 1) {
        if (t < s) sr[t] += sr[t + s];
        __syncthreads();
    }
    if (t == 0) out[b] = sr[0] + h2b[0];
}

// ---------------- launch ----------------
extern "C" void kernel_launch(void* const* d_in, const int* in_sizes, int n_in,
                              void* d_out, int out_size)
{
    const float* at   = (const float*)d_in[0];
    const float* sph  = (const float*)d_in[1];
    const int*   ei   = (const int*)  d_in[2];
    const float* ea   = (const float*)d_in[3];
    const float* Wm   = (const float*)d_in[4];
    const float* bm   = (const float*)d_in[5];
    const float* Wp   = (const float*)d_in[6];
    const float* bp   = (const float*)d_in[7];
    const float* Wq   = (const float*)d_in[8];
    const float* bq   = (const float*)d_in[9];
    const float* Wk   = (const float*)d_in[10];
    const float* bk   = (const float*)d_in[11];
    const float* Wvm  = (const float*)d_in[12];
    const float* bvm  = (const float*)d_in[13];
    const float* Wvp  = (const float*)d_in[14];
    const float* bvp  = (const float*)d_in[15];
    const float* We   = (const float*)d_in[16];
    const float* be   = (const float*)d_in[17];
    const float* ds   = (const float*)d_in[18];
    const float* lng  = (const float*)d_in[19];
    const float* lnb  = (const float*)d_in[20];
    const float* rpW  = (const float*)d_in[21];
    const float* rpb  = (const float*)d_in[22];
    const float* h1W  = (const float*)d_in[23];
    const float* h1b  = (const float*)d_in[24];
    const float* h2W  = (const float*)d_in[25];
    const float* h2b  = (const float*)d_in[26];
    float* out = (float*)d_out;

    size_t layer_smem = (size_t)NN * F2S * 8 + (size_t)NN * ASTR * 4;   // 135168 + 67584 = 202752
    cudaFuncSetAttribute(k_layer, cudaFuncAttributeMaxDynamicSharedMemorySize, (int)layer_smem);

    k_embed<<<BB, 128>>>(at, sph, Wm, bm, Wp, bp);
    k_prep_m<<<dim3(LL, 4, 4), 256>>>(Wq, Wk);
    k_prep_uv<<<LL, 128>>>(Wq, Wk, bq, bk);
    k_wsplit2<<<2*LL, 256>>>(Wvm, Wvp);

    k_layer<<<BB, 512, layer_smem>>>(ei, ea, We, be, ds, lng, lnb, bvm, bvp);

    k_head<<<BB, 128>>>(rpW, rpb, h1W, h1b, h2W, h2b, out);
}

// round 17
// speedup vs baseline: 1.5816x; 1.2161x over previous
#include <cuda_runtime.h>
#include <math.h>
#include <stdint.h>

#define BB   1024
#define NN   128
#define EE   1024
#define HH   128
#define LL   4
#define INDIM 16
#define DIN  19
#define EDIM 4
#define NH   (NN*HH)      // 16384
#define HSQ  (HH*HH)      // 16384
#define ASTR 132

// ---------------- device scratch ----------------
__device__ float  g_mag[(size_t)BB*NH];
__device__ float  g_ph [(size_t)BB*NH];
__device__ float2 g_m2  [(size_t)LL*HSQ];   // pre-split Wq@Wk^T
__device__ float2 g_wvm2[(size_t)LL*HSQ];   // pre-split Wvm
__device__ float2 g_wvp2[(size_t)LL*HSQ];   // pre-split Wvp
__device__ float  g_u[LL*HH];
__device__ float  g_v[LL*HH];
__device__ float  g_c[LL];

// ---------------- helpers ----------------
__device__ __forceinline__ void splitT(float x, uint32_t& hi, uint32_t& lo) {
    uint32_t h = __float_as_uint(x) & 0xffffe000u;
    hi = h;
    lo = __float_as_uint(x - __uint_as_float(h));
}
__device__ __forceinline__ float2 split2(float x) {
    float h = __uint_as_float(__float_as_uint(x) & 0xffffe000u);
    return make_float2(h, x - h);
}
__device__ __forceinline__ void mma8(float* c, const uint32_t* a, uint32_t b0, uint32_t b1) {
    asm volatile("mma.sync.aligned.m16n8k8.row.col.f32.tf32.tf32.f32 "
        "{%0,%1,%2,%3}, {%4,%5,%6,%7}, {%8,%9}, {%0,%1,%2,%3};"
        : "+f"(c[0]), "+f"(c[1]), "+f"(c[2]), "+f"(c[3])
        : "r"(a[0]), "r"(a[1]), "r"(a[2]), "r"(a[3]), "r"(b0), "r"(b1));
}
__device__ __forceinline__ void mma3x(float* c0, float* c1,
                                      const uint32_t* ah0, const uint32_t* al0,
                                      const uint32_t* ah1, const uint32_t* al1,
                                      uint32_t bh0, uint32_t bh1, uint32_t bl0, uint32_t bl1) {
    mma8(c0, ah0, bh0, bh1);
    mma8(c1, ah1, bh0, bh1);
    mma8(c0, ah0, bl0, bl1);
    mma8(c1, ah1, bl0, bl1);
    mma8(c0, al0, bh0, bh1);
    mma8(c1, al1, bh0, bh1);
}
__device__ __forceinline__ void loadA(const float* SA_, int wrm, int k0, int gid, int tig,
                                      uint32_t ah[2][4], uint32_t al[2][4]) {
#pragma unroll
    for (int mt = 0; mt < 2; mt++) {
        int rb = wrm + mt*16;
        splitT(SA_[(rb + gid    )*ASTR + k0 + tig    ], ah[mt][0], al[mt][0]);
        splitT(SA_[(rb + gid + 8)*ASTR + k0 + tig    ], ah[mt][1], al[mt][1]);
        splitT(SA_[(rb + gid    )*ASTR + k0 + tig + 4], ah[mt][2], al[mt][2]);
        splitT(SA_[(rb + gid + 8)*ASTR + k0 + tig + 4], ah[mt][3], al[mt][3]);
    }
}
__device__ __forceinline__ void zacc(float a[2][4][4]) {
#pragma unroll
    for (int i = 0; i < 2; i++)
#pragma unroll
        for (int j = 0; j < 4; j++)
#pragma unroll
            for (int q = 0; q < 4; q++) a[i][j][q] = 0.f;
}

// A(smem) x B^T(smem rows): B[k][n] = Bf[n][k]
__device__ __forceinline__ void gemm_bt(const float* SA_, const float* Bf,
                                        int wrm, int wrn, int gid, int tig, float acc[2][4][4]) {
    zacc(acc);
#pragma unroll
    for (int k0 = 0; k0 < 128; k0 += 8) {
        uint32_t ah[2][4], al[2][4];
        loadA(SA_, wrm, k0, gid, tig, ah, al);
#pragma unroll
        for (int nt = 0; nt < 4; nt++) {
            int nb = wrn + nt*8;
            uint32_t bh0, bl0, bh1, bl1;
            splitT(Bf[(nb + gid)*ASTR + k0 + tig    ], bh0, bl0);
            splitT(Bf[(nb + gid)*ASTR + k0 + tig + 4], bh1, bl1);
            mma3x(acc[0][nt], acc[1][nt], ah[0], al[0], ah[1], al[1], bh0, bh1, bl0, bl1);
        }
    }
}
// A(smem) x {B1, B2}: B1 = smem [k][n] (mag), B2 = gmem fp32 [k][n] stride 128 (ph, coherent)
__device__ __forceinline__ void gemm_dual(const float* SA_, const float* B1f, const float* B2f,
                                          int wrm, int wrn, int gid, int tig,
                                          float accU[2][4][4], float accV[2][4][4]) {
    zacc(accU); zacc(accV);
#pragma unroll
    for (int k0 = 0; k0 < 128; k0 += 8) {
        uint32_t ah[2][4], al[2][4];
        loadA(SA_, wrm, k0, gid, tig, ah, al);
#pragma unroll
        for (int nt = 0; nt < 4; nt++) {
            int nb = wrn + nt*8;
            uint32_t bh0, bl0, bh1, bl1;
            splitT(B1f[(k0 + tig    )*ASTR + nb + gid], bh0, bl0);
            splitT(B1f[(k0 + tig + 4)*ASTR + nb + gid], bh1, bl1);
            mma3x(accU[0][nt], accU[1][nt], ah[0], al[0], ah[1], al[1], bh0, bh1, bl0, bl1);
            splitT(B2f[(k0 + tig    )*HH + nb + gid], bh0, bl0);     // plain coherent load
            splitT(B2f[(k0 + tig + 4)*HH + nb + gid], bh1, bl1);
            mma3x(accV[0][nt], accV[1][nt], ah[0], al[0], ah[1], al[1], bh0, bh1, bl0, bl1);
        }
    }
}
// A(smem) x B(gmem pre-split float2 [k][n] stride 128) — weights, launch-constant
__device__ __forceinline__ void gemm_gw(const float* SA_, const float2* B2,
                                        int wrm, int wrn, int gid, int tig, float acc[2][4][4]) {
    zacc(acc);
#pragma unroll
    for (int k0 = 0; k0 < 128; k0 += 8) {
        uint32_t ah[2][4], al[2][4];
        loadA(SA_, wrm, k0, gid, tig, ah, al);
#pragma unroll
        for (int nt = 0; nt < 4; nt++) {
            int nb = wrn + nt*8;
            float2 b0 = __ldg(&B2[(k0 + tig    )*HH + nb + gid]);
            float2 b1 = __ldg(&B2[(k0 + tig + 4)*HH + nb + gid]);
            mma3x(acc[0][nt], acc[1][nt], ah[0], al[0], ah[1], al[1],
                  __float_as_uint(b0.x), __float_as_uint(b1.x),
                  __float_as_uint(b0.y), __float_as_uint(b1.y));
        }
    }
}

// ---------------- K0: complex embedding (256 threads) ----------------
__global__ void k_embed(const float* __restrict__ at, const float* __restrict__ sph,
                        const float* __restrict__ Wm, const float* __restrict__ bm,
                        const float* __restrict__ Wp, const float* __restrict__ bp)
{
    int b = blockIdx.x, t = threadIdx.x;
    int h = t & 127, grp = t >> 7;           // 2 row-groups of 64
    __shared__ float sx[NN][20];
    for (int i = t; i < NN*DIN; i += blockDim.x) {
        int n = i / DIN, d = i % DIN;
        sx[n][d] = (d < INDIM) ? at[((size_t)b*NN + n)*INDIM + d]
                               : sph[((size_t)b*NN + n)*3 + (d - INDIM)];
    }
    __syncthreads();
    float wm[DIN], wp[DIN];
#pragma unroll
    for (int d = 0; d < DIN; d++) { wm[d] = Wm[d*HH + h]; wp[d] = Wp[d*HH + h]; }
    float bmv = bm[h], bpv = bp[h];
    size_t base = (size_t)b*NH;
    for (int n = grp*64; n < grp*64 + 64; n++) {
        float am = bmv, ap = bpv;
#pragma unroll
        for (int d = 0; d < DIN; d++) { float x = sx[n][d]; am = fmaf(x, wm[d], am); ap = fmaf(x, wp[d], ap); }
        g_mag[base + (size_t)n*HH + h] = am;
        g_ph [base + (size_t)n*HH + h] = ap;
    }
}

// ---------------- prep: M = Wq@Wk^T (pre-split) ----------------
__global__ void k_prep_m(const float* __restrict__ Wq, const float* __restrict__ Wk)
{
    __shared__ float sq[32][129], sk[32][129];
    int l = blockIdx.x, bi = blockIdx.y, bj = blockIdx.z;
    const float* q = Wq + (size_t)l*HSQ + bi*32*HH;
    const float* k = Wk + (size_t)l*HSQ + bj*32*HH;
    int tid = threadIdx.x;
    for (int i = tid; i < 32*128; i += 256) {
        sq[i >> 7][i & 127] = q[(i >> 7)*HH + (i & 127)];
        sk[i >> 7][i & 127] = k[(i >> 7)*HH + (i & 127)];
    }
    __syncthreads();
    int i = tid >> 3, j0 = (tid & 7) * 4;
    for (int jj = 0; jj < 4; jj++) {
        int j = j0 + jj;
        float s = 0.f;
        for (int n = 0; n < 128; n++) s = fmaf(sq[i][n], sk[j][n], s);
        g_m2[(size_t)l*HSQ + (size_t)(bi*32 + i)*HH + bj*32 + j] = split2(s);
    }
}
__global__ void k_prep_uv(const float* __restrict__ Wq, const float* __restrict__ Wk,
                          const float* __restrict__ bqv, const float* __restrict__ bkv)
{
    int l = blockIdx.x, t = threadIdx.x;
    float su = 0.f, sv = 0.f;
    for (int n = 0; n < HH; n++) {
        su = fmaf(Wq[(size_t)l*HSQ + (size_t)t*HH + n], bkv[l*HH + n], su);
        sv = fmaf(Wk[(size_t)l*HSQ + (size_t)t*HH + n], bqv[l*HH + n], sv);
    }
    g_u[l*HH + t] = su;
    g_v[l*HH + t] = sv;
    if (t == 0) {
        float c = 0.f;
        for (int n = 0; n < HH; n++) c = fmaf(bqv[l*HH + n], bkv[l*HH + n], c);
        g_c[l] = c;
    }
}
// grid (8 matrices, 8 slices)
__global__ void k_wsplit2(const float* __restrict__ Wvm, const float* __restrict__ Wvp)
{
    int m = blockIdx.x, s = blockIdx.y;
    int l = m >> 1;
    const float* W = ((m & 1) ? Wvp : Wvm) + (size_t)l*HSQ;
    float2* O = ((m & 1) ? g_wvp2 : g_wvm2) + (size_t)l*HSQ;
    int i0 = s * (HSQ/8);
    for (int i = i0 + threadIdx.x; i < i0 + HSQ/8; i += blockDim.x)
        O[i] = split2(W[i]);
}

// ---------------- fused layer kernel (R10 champion structure) ----------------
__global__ __launch_bounds__(512) void k_layer(
    const int* __restrict__ ei, const float* __restrict__ ea,
    const float* __restrict__ We, const float* __restrict__ be,
    const float* __restrict__ ds,
    const float* __restrict__ lng, const float* __restrict__ lnb,
    const float* __restrict__ bvm, const float* __restrict__ bvp)
{
    extern __shared__ float sm[];
    float* S1 = sm;                 // mag (persistent)
    float* S2 = sm +   NN*ASTR;     // t / scores / probs / V
    float* S3 = sm + 2*NN*ASTR;     // bias / U
    __shared__ float sru[NN], srv[NN];

    int b = blockIdx.x, tid = threadIdx.x;
    int wid = tid >> 5, lane = tid & 31;
    int gid = lane >> 2, tig = lane & 3;
    int wrm = (wid & 3) * 32, wrn = (wid >> 2) * 32;
    size_t base = (size_t)b*NH;
    float* php = g_ph + base;
    const float scale = 0.08838834764831845f;   // 1/sqrt(128)

    // load mag into S1
#pragma unroll
    for (int it = 0; it < 8; it++) {
        int idx = tid + 512*it;
        int r = idx >> 5, c = (idx & 31) * 4;
        *(float4*)(S1 + r*ASTR + c) = *(const float4*)(g_mag + base + (size_t)r*HH + c);
    }
    __syncthreads();

    float acc[2][4][4];
    float accV[2][4][4];

#pragma unroll 1
    for (int l = 0; l < LL; l++) {
        float cL = __ldg(&g_c[l]);

        // ---- zero S3 + compute ru/rv ----
        for (int i = tid; i < NN*ASTR/4; i += 512) ((float4*)S3)[i] = make_float4(0.f, 0.f, 0.f, 0.f);
        {
            int row = tid >> 2, qtr = tid & 3;
            const float* uu = g_u + l*HH + 32*qtr;
            const float* vv = g_v + l*HH + 32*qtr;
            const float* rowp = S1 + row*ASTR + 32*qtr;
            float pu = 0.f, pv = 0.f;
#pragma unroll
            for (int j = 0; j < 32; j++) {
                float mv = rowp[j];
                pu = fmaf(mv, __ldg(uu + j), pu);
                pv = fmaf(mv, __ldg(vv + j), pv);
            }
            pu += __shfl_xor_sync(0xffffffffu, pu, 1);
            pu += __shfl_xor_sync(0xffffffffu, pu, 2);
            pv += __shfl_xor_sync(0xffffffffu, pv, 1);
            pv += __shfl_xor_sync(0xffffffffu, pv, 2);
            if (qtr == 0) { sru[row] = pu; srv[row] = pv; }
        }
        __syncthreads();

        // ---- edge bias scatter into S3 ----
        {
            float w0 = We[l*4+0], w1 = We[l*4+1], w2 = We[l*4+2], w3 = We[l*4+3];
            float beL = be[l], dsL = ds[l];
            for (int e = tid; e < EE; e += 512) {
                int i0 = ei[(size_t)b*2*EE + e];
                int j0 = ei[(size_t)b*2*EE + EE + e];
                const float* a = ea + ((size_t)b*EE + e)*EDIM;
                float v = fmaf(a[0], w0, fmaf(a[1], w1, fmaf(a[2], w2, fmaf(a[3], w3, beL)))) + dsL*a[0];
                atomicAdd(&S3[i0*ASTR + j0], v);
            }
        }
        __syncthreads();

        // ---- phase 2: t = mag @ M -> S2 ----
        gemm_gw(S1, g_m2 + (size_t)l*HSQ, wrm, wrn, gid, tig, acc);
#pragma unroll
        for (int mt = 0; mt < 2; mt++) {
            int r0 = wrm + mt*16 + gid;
#pragma unroll
            for (int nt = 0; nt < 4; nt++) {
                int c = wrn + nt*8 + 2*tig;
                *(float2*)(S2 + r0*ASTR + c)     = make_float2(acc[mt][nt][0], acc[mt][nt][1]);
                *(float2*)(S2 + (r0+8)*ASTR + c) = make_float2(acc[mt][nt][2], acc[mt][nt][3]);
            }
        }
        __syncthreads();

        // ---- phase 3: scores = (t @ mag^T + ru + rv + c)*scale + bias, in-place S2 ----
        gemm_bt(S2, S1, wrm, wrn, gid, tig, acc);
        __syncthreads();   // all reads of t done before in-place overwrite
#pragma unroll
        for (int mt = 0; mt < 2; mt++) {
            int r0 = wrm + mt*16 + gid, r1 = r0 + 8;
#pragma unroll
            for (int nt = 0; nt < 4; nt++) {
                int c = wrn + nt*8 + 2*tig;
                float rv0 = srv[c], rv1 = srv[c + 1];
                float s00 = fmaf(acc[mt][nt][0] + sru[r0] + rv0 + cL, scale, S3[r0*ASTR + c]);
                float s01 = fmaf(acc[mt][nt][1] + sru[r0] + rv1 + cL, scale, S3[r0*ASTR + c + 1]);
                float s10 = fmaf(acc[mt][nt][2] + sru[r1] + rv0 + cL, scale, S3[r1*ASTR + c]);
                float s11 = fmaf(acc[mt][nt][3] + sru[r1] + rv1 + cL, scale, S3[r1*ASTR + c + 1]);
                *(float2*)(S2 + r0*ASTR + c) = make_float2(s00, s01);
                *(float2*)(S2 + r1*ASTR + c) = make_float2(s10, s11);
            }
        }
        __syncthreads();

        // ---- phase 4: softmax rows of S2 (4 threads/row) ----
        {
            int row = tid >> 2, qtr = tid & 3;
            float* rp = S2 + row*ASTR + 32*qtr;
            float m = -1e30f;
#pragma unroll
            for (int j = 0; j < 8; j++) {
                float4 v = *(const float4*)(rp + 4*j);
                m = fmaxf(m, fmaxf(fmaxf(v.x, v.y), fmaxf(v.z, v.w)));
            }
            m = fmaxf(m, __shfl_xor_sync(0xffffffffu, m, 1));
            m = fmaxf(m, __shfl_xor_sync(0xffffffffu, m, 2));
            float s = 0.f;
#pragma unroll
            for (int j = 0; j < 8; j++) {
                float4 v = *(float4*)(rp + 4*j);
                v.x = __expf(v.x - m); v.y = __expf(v.y - m);
                v.z = __expf(v.z - m); v.w = __expf(v.w - m);
                s += v.x + v.y + v.z + v.w;
                *(float4*)(rp + 4*j) = v;
            }
            s += __shfl_xor_sync(0xffffffffu, s, 1);
            s += __shfl_xor_sync(0xffffffffu, s, 2);
            float inv = 1.f / s;
#pragma unroll
            for (int j = 0; j < 8; j++) {
                float4 v = *(float4*)(rp + 4*j);
                v.x *= inv; v.y *= inv; v.z *= inv; v.w *= inv;
                *(float4*)(rp + 4*j) = v;
            }
        }
        __syncthreads();

        // ---- phase 5+7: U = P @ mag(S1), V = P @ ph(gmem, coherent) ----
        gemm_dual(S2, S1, php, wrm, wrn, gid, tig, acc, accV);
        // U -> S3 (bias dead)
#pragma unroll
        for (int mt = 0; mt < 2; mt++) {
            int r0 = wrm + mt*16 + gid;
#pragma unroll
            for (int nt = 0; nt < 4; nt++) {
                int c = wrn + nt*8 + 2*tig;
                *(float2*)(S3 + r0*ASTR + c)     = make_float2(acc[mt][nt][0], acc[mt][nt][1]);
                *(float2*)(S3 + (r0+8)*ASTR + c) = make_float2(acc[mt][nt][2], acc[mt][nt][3]);
            }
        }
        __syncthreads();   // all reads of P (S2) complete
        // V -> S2 (overwrites P)
#pragma unroll
        for (int mt = 0; mt < 2; mt++) {
            int r0 = wrm + mt*16 + gid;
#pragma unroll
            for (int nt = 0; nt < 4; nt++) {
                int c = wrn + nt*8 + 2*tig;
                *(float2*)(S2 + r0*ASTR + c)     = make_float2(accV[mt][nt][0], accV[mt][nt][1]);
                *(float2*)(S2 + (r0+8)*ASTR + c) = make_float2(accV[mt][nt][2], accV[mt][nt][3]);
            }
        }
        __syncthreads();

        // ---- phase 6: new_mag = U(S3) @ Wvm + bvm + mag -> S1 ----
        gemm_gw(S3, g_wvm2 + (size_t)l*HSQ, wrm, wrn, gid, tig, acc);
#pragma unroll
        for (int mt = 0; mt < 2; mt++) {
            int r0 = wrm + mt*16 + gid, r1 = r0 + 8;
#pragma unroll
            for (int nt = 0; nt < 4; nt++) {
                int c = wrn + nt*8 + 2*tig;
                float bv0 = __ldg(bvm + l*HH + c), bv1 = __ldg(bvm + l*HH + c + 1);
                float2 o0 = *(float2*)(S1 + r0*ASTR + c);
                float2 o1 = *(float2*)(S1 + r1*ASTR + c);
                o0.x += acc[mt][nt][0] + bv0; o0.y += acc[mt][nt][1] + bv1;
                o1.x += acc[mt][nt][2] + bv0; o1.y += acc[mt][nt][3] + bv1;
                *(float2*)(S1 + r0*ASTR + c) = o0;
                *(float2*)(S1 + r1*ASTR + c) = o1;
            }
        }
        __syncthreads();

        // ---- LayerNorm rows of S1 (4 threads/row) ----
        {
            int row = tid >> 2, qtr = tid & 3;
            float* rp = S1 + row*ASTR + 32*qtr;
            float su = 0.f;
#pragma unroll
            for (int j = 0; j < 8; j++) {
                float4 v = *(const float4*)(rp + 4*j);
                su += v.x + v.y + v.z + v.w;
            }
            su += __shfl_xor_sync(0xffffffffu, su, 1);
            su += __shfl_xor_sync(0xffffffffu, su, 2);
            float mu = su * (1.f/128.f);
            float var = 0.f;
#pragma unroll
            for (int j = 0; j < 8; j++) {
                float4 v = *(const float4*)(rp + 4*j);
                float d0 = v.x - mu, d1 = v.y - mu, d2 = v.z - mu, d3 = v.w - mu;
                var = fmaf(d0, d0, var); var = fmaf(d1, d1, var);
                var = fmaf(d2, d2, var); var = fmaf(d3, d3, var);
            }
            var += __shfl_xor_sync(0xffffffffu, var, 1);
            var += __shfl_xor_sync(0xffffffffu, var, 2);
            float rs = rsqrtf(var * (1.f/128.f) + 1e-5f);
            const float* gp  = lng + l*HH + 32*qtr;
            const float* bp2 = lnb + l*HH + 32*qtr;
#pragma unroll
            for (int j = 0; j < 8; j++) {
                float4 v = *(float4*)(rp + 4*j);
                float4 g = *(const float4*)(gp + 4*j);
                float4 be2 = *(const float4*)(bp2 + 4*j);
                v.x = fmaf(g.x, (v.x - mu)*rs, be2.x);
                v.y = fmaf(g.y, (v.y - mu)*rs, be2.y);
                v.z = fmaf(g.z, (v.z - mu)*rs, be2.z);
                v.w = fmaf(g.w, (v.w - mu)*rs, be2.w);
                *(float4*)(rp + 4*j) = v;
            }
        }
        __syncthreads();

        // ---- phase 8: new_ph = V @ Wvp + bvp + ph -> gmem ph ----
        gemm_gw(S2, g_wvp2 + (size_t)l*HSQ, wrm, wrn, gid, tig, acc);
#pragma unroll
        for (int mt = 0; mt < 2; mt++) {
            int r0 = wrm + mt*16 + gid, r1 = r0 + 8;
#pragma unroll
            for (int nt = 0; nt < 4; nt++) {
                int c = wrn + nt*8 + 2*tig;
                float bv0 = __ldg(bvp + l*HH + c), bv1 = __ldg(bvp + l*HH + c + 1);
                float2 o0 = *(float2*)(php + (size_t)r0*HH + c);
                float2 o1 = *(float2*)(php + (size_t)r1*HH + c);
                o0.x += acc[mt][nt][0] + bv0; o0.y += acc[mt][nt][1] + bv1;
                o1.x += acc[mt][nt][2] + bv0; o1.y += acc[mt][nt][3] + bv1;
                *(float2*)(php + (size_t)r0*HH + c) = o0;
                *(float2*)(php + (size_t)r1*HH + c) = o1;
            }
        }
        __syncthreads();
    }

    // write final mag back
#pragma unroll
    for (int it = 0; it < 8; it++) {
        int idx = tid + 512*it;
        int r = idx >> 5, c = (idx & 31) * 4;
        *(float4*)(g_mag + base + (size_t)r*HH + c) = *(const float4*)(S1 + r*ASTR + c);
    }
}

// ---------------- K3: head (fast sincos) ----------------
__global__ void k_head(const float* __restrict__ rpW, const float* __restrict__ rpb,
                       const float* __restrict__ h1W, const float* __restrict__ h1b,
                       const float* __restrict__ h2W, const float* __restrict__ h2b,
                       float* __restrict__ out)
{
    int b = blockIdx.x, t = threadIdx.x;
    __shared__ float sS[2*HH];
    __shared__ float sp[2*HH];
    __shared__ float sr[HH];
    size_t base = (size_t)b*NH;

    float ac = 0.f, as = 0.f;
    for (int n = 0; n < NN; n++) {
        float m = g_mag[base + (size_t)n*HH + t];
        float p = g_ph [base + (size_t)n*HH + t];
        float si, co;
        __sincosf(p, &si, &co);
        ac = fmaf(m, co, ac);
        as = fmaf(m, si, as);
    }
    sS[t] = ac; sS[HH + t] = as;
    __syncthreads();

    float d = 0.f;
    for (int c = 0; c < 2*HH; c++) d = fmaf(sS[c], rpW[(size_t)c*HH + t], d);
    float sumr = d + 128.f * rpb[t];
    sp[t]      = sumr * (1.f/128.f);
    sp[HH + t] = sumr;
    __syncthreads();

    float hv = h1b[t];
    for (int c = 0; c < 2*HH; c++) hv = fmaf(sp[c], h1W[(size_t)c*HH + t], hv);
    hv = hv / (1.f + expf(-hv));
    sr[t] = hv * h2W[t];
    __syncthreads();

    for (int s = 64; s >= 1; s >>= 1) {
        if (t < s) sr[t] += sr[t + s];
        __syncthreads();
    }
    if (t == 0) out[b] = sr[0] + h2b[0];
}

// ---------------- launch ----------------
extern "C" void kernel_launch(void* const* d_in, const int* in_sizes, int n_in,
                              void* d_out, int out_size)
{
    const float* at   = (const float*)d_in[0];
    const float* sph  = (const float*)d_in[1];
    const int*   ei   = (const int*)  d_in[2];
    const float* ea   = (const float*)d_in[3];
    const float* Wm   = (const float*)d_in[4];
    const float* bm   = (const float*)d_in[5];
    const float* Wp   = (const float*)d_in[6];
    const float* bp   = (const float*)d_in[7];
    const float* Wq   = (const float*)d_in[8];
    const float* bq   = (const float*)d_in[9];
    const float* Wk   = (const float*)d_in[10];
    const float* bk   = (const float*)d_in[11];
    const float* Wvm  = (const float*)d_in[12];
    const float* bvm  = (const float*)d_in[13];
    const float* Wvp  = (const float*)d_in[14];
    const float* bvp  = (const float*)d_in[15];
    const float* We   = (const float*)d_in[16];
    const float* be   = (const float*)d_in[17];
    const float* ds   = (const float*)d_in[18];
    const float* lng  = (const float*)d_in[19];
    const float* lnb  = (const float*)d_in[20];
    const float* rpW  = (const float*)d_in[21];
    const float* rpb  = (const float*)d_in[22];
    const float* h1W  = (const float*)d_in[23];
    const float* h1b  = (const float*)d_in[24];
    const float* h2W  = (const float*)d_in[25];
    const float* h2b  = (const float*)d_in[26];
    float* out = (float*)d_out;

    size_t layer_smem = (size_t)3 * NN * ASTR * sizeof(float);   // 202752
    cudaFuncSetAttribute(k_layer, cudaFuncAttributeMaxDynamicSharedMemorySize, (int)layer_smem);

    k_embed<<<BB, 256>>>(at, sph, Wm, bm, Wp, bp);
    k_prep_m<<<dim3(LL, 4, 4), 256>>>(Wq, Wk);
    k_prep_uv<<<LL, 128>>>(Wq, Wk, bq, bk);
    k_wsplit2<<<dim3(2*LL, 8), 256>>>(Wvm, Wvp);

    k_layer<<<BB, 512, layer_smem>>>(ei, ea, We, be, ds, lng, lnb, bvm, bvp);

    k_head<<<BB, 128>>>(rpW, rpb, h1W, h1b, h2W, h2b, out);
}